// round 5
// baseline (speedup 1.0000x reference)
#include <cuda_runtime.h>
#include <cstdint>

#define NAG 1024
#define NJC 16          // j-chunks of 64
#define TI  128         // i's per CTA
#define THREADS 256

__device__ float g_U[NAG * 128];
__device__ float g_Q[NAG * 128];
__device__ float g_partial[NJC * NAG * 64];

// ---------------- helpers ----------------
__device__ __forceinline__ uint32_t f2tf32(float f) {
    uint32_t r;
    asm("cvt.rna.tf32.f32 %0, %1;" : "=r"(r) : "f"(f));
    return r;
}

// mma.sync m16n8k8 tf32: D += A(16x8 row) * B(8x8 col)
__device__ __forceinline__ void mma_tf32(float* d,
                                         uint32_t a0, uint32_t a1, uint32_t a2, uint32_t a3,
                                         uint32_t b0, uint32_t b1) {
    asm volatile(
        "mma.sync.aligned.m16n8k8.row.col.f32.tf32.tf32.f32 "
        "{%0,%1,%2,%3}, {%4,%5,%6,%7}, {%8,%9}, {%0,%1,%2,%3};"
        : "+f"(d[0]), "+f"(d[1]), "+f"(d[2]), "+f"(d[3])
        : "r"(a0), "r"(a1), "r"(a2), "r"(a3), "r"(b0), "r"(b1));
}

// ---------------- Kernel 1: precompute U, Q ----------------
// U[a][m] = hidden[a]@W1[0:64,m] + b1[m] + (b_e + ends[a]@W_e)@W1[64:80,m]
// Q[a][m] = (ends[a]@W_e)@W1[64:80,m]
__global__ void precompute_kernel(const float* __restrict__ hidden,
                                  const float* __restrict__ track,
                                  const float* __restrict__ W_e,
                                  const float* __restrict__ b_e,
                                  const float* __restrict__ W1,
                                  const float* __restrict__ b1) {
    __shared__ float sh[64];
    __shared__ float sP[16];
    int a = blockIdx.x;
    int m = threadIdx.x;  // 0..127
    if (m < 64) sh[m] = hidden[a * 64 + m];
    if (m < 16) {
        float e0 = track[a * 16 + 14];  // group_track[a][7][0]
        float e1 = track[a * 16 + 15];  // group_track[a][7][1]
        sP[m] = e0 * W_e[m] + e1 * W_e[16 + m];
    }
    __syncthreads();
    float acc = b1[m];
#pragma unroll 8
    for (int h = 0; h < 64; h++) acc = fmaf(sh[h], W1[h * 128 + m], acc);
    float q = 0.f;
#pragma unroll
    for (int e = 0; e < 16; e++) {
        float w = W1[(64 + e) * 128 + m];
        q = fmaf(sP[e], w, q);
        acc = fmaf(b_e[e], w, acc);
    }
    g_Q[a * 128 + m] = q;
    g_U[a * 128 + m] = acc + q;
}

// ---------------- Kernel 2: Zpre = relu(U[j]-Q[i]) @ W2, max over j-chunk ----------------
// CTA: 8 warps = 4 j-groups(16 rows) x 2 n-halves(32 cols). 64j x 64n x 128k per i.
__global__ void __launch_bounds__(THREADS, 1)
main_kernel(const float* __restrict__ W2) {
    __shared__ float sred[2][4 * 64];   // [buf][j-group][64 n]

    const int tid  = threadIdx.x;
    const int wid  = tid >> 5;
    const int lane = tid & 31;
    const int g = lane >> 2;            // groupID (0..7)
    const int c = lane & 3;             // threadID in group
    const int mg = wid >> 1;            // j-group 0..3
    const int nh = wid & 1;             // n-half 0..1

    const int jc    = blockIdx.x & (NJC - 1);   // j-chunk
    const int ibase = (blockIdx.x >> 4) * TI;   // i-group
    const int jbase = jc * 64;
    const int j0 = jbase + mg * 16 + g;         // first A row this thread covers

    // U slice in registers: rows j0, j0+8; cols c + 4t (t=0..31)
    float Ua[32], Ub[32];
    {
        const float* u0 = g_U + j0 * 128 + c;
        const float* u1 = g_U + (j0 + 8) * 128 + c;
#pragma unroll
        for (int t = 0; t < 32; t++) {
            Ua[t] = __ldg(u0 + 4 * t);
            Ub[t] = __ldg(u1 + 4 * t);
        }
    }

    // W2 fragments in registers (tf32), invariant over i.
    // b0 = W2[k=8ks+c][n], b1 = W2[k=8ks+c+4][n], n = nh*32 + nt*8 + g
    uint32_t Wf[4][16][2];
#pragma unroll
    for (int nt = 0; nt < 4; nt++) {
        const int n = nh * 32 + nt * 8 + g;
#pragma unroll
        for (int ks = 0; ks < 16; ks++) {
            Wf[nt][ks][0] = f2tf32(__ldg(W2 + (8 * ks + c) * 64 + n));
            Wf[nt][ks][1] = f2tf32(__ldg(W2 + (8 * ks + c + 4) * 64 + n));
        }
    }

    for (int ii = 0; ii < TI; ii++) {
        const float* Qrow = g_Q + (ibase + ii) * 128;
        float d[4][4];
#pragma unroll
        for (int nt = 0; nt < 4; nt++)
#pragma unroll
            for (int r = 0; r < 4; r++) d[nt][r] = 0.f;

#pragma unroll
        for (int ks = 0; ks < 16; ks++) {
            const float q0 = __ldg(Qrow + 8 * ks + c);
            const float q1 = __ldg(Qrow + 8 * ks + 4 + c);
            const uint32_t a0 = f2tf32(fmaxf(Ua[2 * ks]     - q0, 0.f));
            const uint32_t a1 = f2tf32(fmaxf(Ub[2 * ks]     - q0, 0.f));
            const uint32_t a2 = f2tf32(fmaxf(Ua[2 * ks + 1] - q1, 0.f));
            const uint32_t a3 = f2tf32(fmaxf(Ub[2 * ks + 1] - q1, 0.f));
#pragma unroll
            for (int nt = 0; nt < 4; nt++)
                mma_tf32(d[nt], a0, a1, a2, a3, Wf[nt][ks][0], Wf[nt][ks][1]);
        }

        // ---- max over j ----
        // In-thread: combine rows j0 and j0+8.
        float m0[4], m1[4];
#pragma unroll
        for (int nt = 0; nt < 4; nt++) {
            m0[nt] = fmaxf(d[nt][0], d[nt][2]);   // col 8nt+2c   (+ n-half offset)
            m1[nt] = fmaxf(d[nt][1], d[nt][3]);   // col 8nt+2c+1
        }
        // Reduce over the 8 row-groups (lanes differing in bits 2..4).
#pragma unroll
        for (int ofs = 4; ofs <= 16; ofs <<= 1) {
#pragma unroll
            for (int nt = 0; nt < 4; nt++) {
                m0[nt] = fmaxf(m0[nt], __shfl_xor_sync(0xffffffffu, m0[nt], ofs));
                m1[nt] = fmaxf(m1[nt], __shfl_xor_sync(0xffffffffu, m1[nt], ofs));
            }
        }
        const int buf = ii & 1;
        if (lane < 4) {  // c == lane, g == 0
#pragma unroll
            for (int nt = 0; nt < 4; nt++) {
                sred[buf][mg * 64 + nh * 32 + nt * 8 + 2 * lane]     = m0[nt];
                sred[buf][mg * 64 + nh * 32 + nt * 8 + 2 * lane + 1] = m1[nt];
            }
        }
        __syncthreads();
        if (tid < 64) {
            float v = fmaxf(fmaxf(sred[buf][tid], sred[buf][64 + tid]),
                            fmaxf(sred[buf][128 + tid], sred[buf][192 + tid]));
            g_partial[jc * (NAG * 64) + (ibase + ii) * 64 + tid] = v;
        }
        // double-buffered sred: next iteration writes buf^1, safe without 2nd sync
    }
}

// ---------------- Kernel 3: combine over j-chunks + relu(+b2) ----------------
__global__ void combine_kernel(const float* __restrict__ b2, float* __restrict__ out) {
    int idx = blockIdx.x * 256 + threadIdx.x;  // 0..65535 = i*64+n
    int n = idx & 63;
    float m = g_partial[idx];
#pragma unroll
    for (int ch = 1; ch < NJC; ch++)
        m = fmaxf(m, g_partial[ch * (NAG * 64) + idx]);
    out[idx] = fmaxf(m + b2[n], 0.f);
}

extern "C" void kernel_launch(void* const* d_in, const int* in_sizes, int n_in,
                              void* d_out, int out_size) {
    const float* hidden = (const float*)d_in[0];
    const float* track  = (const float*)d_in[1];
    const float* W_e    = (const float*)d_in[2];
    const float* b_e    = (const float*)d_in[3];
    const float* W1     = (const float*)d_in[4];
    const float* b1     = (const float*)d_in[5];
    const float* W2     = (const float*)d_in[6];
    const float* b2     = (const float*)d_in[7];
    float* out = (float*)d_out;

    precompute_kernel<<<NAG, 128>>>(hidden, track, W_e, b_e, W1, b1);
    main_kernel<<<NJC * (NAG / TI), THREADS>>>(W2);   // 16 x 8 = 128 CTAs
    combine_kernel<<<NAG * 64 / 256, 256>>>(b2, out);
}

// round 6
// speedup vs baseline: 1.6375x; 1.6375x over previous
#include <cuda_runtime.h>
#include <cstdint>

#define NAG 1024
#define NJC 16          // j-chunks of 64
#define TI  128         // i's per CTA
#define THREADS 256

__device__ float g_U[NAG * 128];
__device__ float g_Q[NAG * 128];
__device__ float g_partial[NJC * NAG * 64];

// ---------------- helpers ----------------
// pack two f32 -> f16x2 (lo = first arg, hi = second arg), round-nearest
__device__ __forceinline__ uint32_t pack_h2(float lo, float hi) {
    uint32_t r;
    asm("cvt.rn.f16x2.f32 %0, %1, %2;" : "=r"(r) : "f"(hi), "f"(lo));
    return r;
}

// mma.sync m16n8k16 f16, f32 accum: D += A(16x16 row) * B(16x8 col)
__device__ __forceinline__ void mma_f16(float* d,
                                        uint32_t a0, uint32_t a1, uint32_t a2, uint32_t a3,
                                        uint32_t b0, uint32_t b1) {
    asm volatile(
        "mma.sync.aligned.m16n8k16.row.col.f32.f16.f16.f32 "
        "{%0,%1,%2,%3}, {%4,%5,%6,%7}, {%8,%9}, {%0,%1,%2,%3};"
        : "+f"(d[0]), "+f"(d[1]), "+f"(d[2]), "+f"(d[3])
        : "r"(a0), "r"(a1), "r"(a2), "r"(a3), "r"(b0), "r"(b1));
}

// ---------------- Kernel 1: precompute U, Q ----------------
// U[a][m] = hidden[a]@W1[0:64,m] + b1[m] + (b_e + ends[a]@W_e)@W1[64:80,m]
// Q[a][m] = (ends[a]@W_e)@W1[64:80,m]
__global__ void precompute_kernel(const float* __restrict__ hidden,
                                  const float* __restrict__ track,
                                  const float* __restrict__ W_e,
                                  const float* __restrict__ b_e,
                                  const float* __restrict__ W1,
                                  const float* __restrict__ b1) {
    __shared__ float sh[64];
    __shared__ float sP[16];
    int a = blockIdx.x;
    int m = threadIdx.x;  // 0..127
    if (m < 64) sh[m] = hidden[a * 64 + m];
    if (m < 16) {
        float e0 = track[a * 16 + 14];  // group_track[a][7][0]
        float e1 = track[a * 16 + 15];  // group_track[a][7][1]
        sP[m] = e0 * W_e[m] + e1 * W_e[16 + m];
    }
    __syncthreads();
    float acc = b1[m];
#pragma unroll 8
    for (int h = 0; h < 64; h++) acc = fmaf(sh[h], W1[h * 128 + m], acc);
    float q = 0.f;
#pragma unroll
    for (int e = 0; e < 16; e++) {
        float w = W1[(64 + e) * 128 + m];
        q = fmaf(sP[e], w, q);
        acc = fmaf(b_e[e], w, acc);
    }
    g_Q[a * 128 + m] = q;
    g_U[a * 128 + m] = acc + q;
}

// ---------------- Kernel 2: Zpre = relu(U[j]-Q[i]) @ W2, max over j-chunk ----------------
// CTA: 8 warps = 4 j-groups(16 rows) x 2 n-halves(32 cols). 64j x 64n x 128k per i.
// fp16 m16n8k16: 8 k-steps of 16.
__global__ void __launch_bounds__(THREADS, 1)
main_kernel(const float* __restrict__ W2) {
    __shared__ float sred[2][4 * 64];   // [buf][j-group][64 n]

    const int tid  = threadIdx.x;
    const int wid  = tid >> 5;
    const int lane = tid & 31;
    const int g = lane >> 2;            // groupID (0..7)
    const int c = lane & 3;             // threadID in group
    const int mg = wid >> 1;            // j-group 0..3
    const int nh = wid & 1;             // n-half 0..1

    const int jc    = blockIdx.x & (NJC - 1);   // j-chunk
    const int ibase = (blockIdx.x >> 4) * TI;   // i-group
    const int j0 = jc * 64 + mg * 16 + g;       // first A row this thread covers

    // U slice in registers, fp32.
    // Ua[4*ks + {0,1,2,3}] = U[j0][16ks + {2c, 2c+1, 2c+8, 2c+9}]; Ub: row j0+8.
    float Ua[32], Ub[32];
    {
        const float* u0 = g_U + j0 * 128;
        const float* u1 = g_U + (j0 + 8) * 128;
#pragma unroll
        for (int ks = 0; ks < 8; ks++) {
            float2 p;
            p = *(const float2*)(u0 + 16 * ks + 2 * c);     Ua[4*ks+0]=p.x; Ua[4*ks+1]=p.y;
            p = *(const float2*)(u0 + 16 * ks + 2 * c + 8); Ua[4*ks+2]=p.x; Ua[4*ks+3]=p.y;
            p = *(const float2*)(u1 + 16 * ks + 2 * c);     Ub[4*ks+0]=p.x; Ub[4*ks+1]=p.y;
            p = *(const float2*)(u1 + 16 * ks + 2 * c + 8); Ub[4*ks+2]=p.x; Ub[4*ks+3]=p.y;
        }
    }

    // W2 fragments (f16x2), invariant over i.
    // Wf[nt][ks][0]: rows 16ks+2c, 16ks+2c+1 (lo,hi), col n; Wf[..][1]: rows +8.
    uint32_t Wf[4][8][2];
#pragma unroll
    for (int nt = 0; nt < 4; nt++) {
        const int n = nh * 32 + nt * 8 + g;
#pragma unroll
        for (int ks = 0; ks < 8; ks++) {
            const int r = 16 * ks + 2 * c;
            Wf[nt][ks][0] = pack_h2(__ldg(W2 + r * 64 + n),       __ldg(W2 + (r + 1) * 64 + n));
            Wf[nt][ks][1] = pack_h2(__ldg(W2 + (r + 8) * 64 + n), __ldg(W2 + (r + 9) * 64 + n));
        }
    }

    // Prefetch Q for first i: q[2*ks+0] = cols 16ks+2c..2c+1, q[2*ks+1] = +8
    float2 qv[16];
    {
        const float* Qrow = g_Q + ibase * 128;
#pragma unroll
        for (int ks = 0; ks < 8; ks++) {
            qv[2*ks+0] = __ldg((const float2*)(Qrow + 16 * ks + 2 * c));
            qv[2*ks+1] = __ldg((const float2*)(Qrow + 16 * ks + 2 * c + 8));
        }
    }

#pragma unroll 1
    for (int ii = 0; ii < TI; ii++) {
        // Stage current Q, start prefetch of next row.
        float2 q[16];
#pragma unroll
        for (int t = 0; t < 16; t++) q[t] = qv[t];
        if (ii + 1 < TI) {
            const float* Qn = g_Q + (ibase + ii + 1) * 128;
#pragma unroll
            for (int ks = 0; ks < 8; ks++) {
                qv[2*ks+0] = __ldg((const float2*)(Qn + 16 * ks + 2 * c));
                qv[2*ks+1] = __ldg((const float2*)(Qn + 16 * ks + 2 * c + 8));
            }
        }

        float d[4][4];
#pragma unroll
        for (int nt = 0; nt < 4; nt++)
#pragma unroll
            for (int r = 0; r < 4; r++) d[nt][r] = 0.f;

#pragma unroll
        for (int ks = 0; ks < 8; ks++) {
            const float2 q01 = q[2*ks+0];
            const float2 q89 = q[2*ks+1];
            const uint32_t a0 = pack_h2(fmaxf(Ua[4*ks+0] - q01.x, 0.f),
                                        fmaxf(Ua[4*ks+1] - q01.y, 0.f));
            const uint32_t a1 = pack_h2(fmaxf(Ub[4*ks+0] - q01.x, 0.f),
                                        fmaxf(Ub[4*ks+1] - q01.y, 0.f));
            const uint32_t a2 = pack_h2(fmaxf(Ua[4*ks+2] - q89.x, 0.f),
                                        fmaxf(Ua[4*ks+3] - q89.y, 0.f));
            const uint32_t a3 = pack_h2(fmaxf(Ub[4*ks+2] - q89.x, 0.f),
                                        fmaxf(Ub[4*ks+3] - q89.y, 0.f));
#pragma unroll
            for (int nt = 0; nt < 4; nt++)
                mma_f16(d[nt], a0, a1, a2, a3, Wf[nt][ks][0], Wf[nt][ks][1]);
        }

        // ---- max over j ----
        // D layout: d0:(g,2c) d1:(g,2c+1) d2:(g+8,2c) d3:(g+8,2c+1)
        float m0[4], m1[4];
#pragma unroll
        for (int nt = 0; nt < 4; nt++) {
            m0[nt] = fmaxf(d[nt][0], d[nt][2]);
            m1[nt] = fmaxf(d[nt][1], d[nt][3]);
        }
#pragma unroll
        for (int ofs = 4; ofs <= 16; ofs <<= 1) {
#pragma unroll
            for (int nt = 0; nt < 4; nt++) {
                m0[nt] = fmaxf(m0[nt], __shfl_xor_sync(0xffffffffu, m0[nt], ofs));
                m1[nt] = fmaxf(m1[nt], __shfl_xor_sync(0xffffffffu, m1[nt], ofs));
            }
        }
        const int buf = ii & 1;
        if (lane < 4) {  // lane == c, g == 0
#pragma unroll
            for (int nt = 0; nt < 4; nt++) {
                sred[buf][mg * 64 + nh * 32 + nt * 8 + 2 * lane]     = m0[nt];
                sred[buf][mg * 64 + nh * 32 + nt * 8 + 2 * lane + 1] = m1[nt];
            }
        }
        __syncthreads();
        if (tid < 64) {
            float v = fmaxf(fmaxf(sred[buf][tid], sred[buf][64 + tid]),
                            fmaxf(sred[buf][128 + tid], sred[buf][192 + tid]));
            g_partial[jc * (NAG * 64) + (ibase + ii) * 64 + tid] = v;
        }
        // sred double-buffered: next iteration writes buf^1, safe without 2nd sync
    }
}

// ---------------- Kernel 3: combine over j-chunks + relu(+b2) ----------------
__global__ void combine_kernel(const float* __restrict__ b2, float* __restrict__ out) {
    int idx = blockIdx.x * 256 + threadIdx.x;  // 0..65535 = i*64+n
    int n = idx & 63;
    float m = g_partial[idx];
#pragma unroll
    for (int ch = 1; ch < NJC; ch++)
        m = fmaxf(m, g_partial[ch * (NAG * 64) + idx]);
    out[idx] = fmaxf(m + b2[n], 0.f);
}

extern "C" void kernel_launch(void* const* d_in, const int* in_sizes, int n_in,
                              void* d_out, int out_size) {
    const float* hidden = (const float*)d_in[0];
    const float* track  = (const float*)d_in[1];
    const float* W_e    = (const float*)d_in[2];
    const float* b_e    = (const float*)d_in[3];
    const float* W1     = (const float*)d_in[4];
    const float* b1     = (const float*)d_in[5];
    const float* W2     = (const float*)d_in[6];
    const float* b2     = (const float*)d_in[7];
    float* out = (float*)d_out;

    precompute_kernel<<<NAG, 128>>>(hidden, track, W_e, b_e, W1, b1);
    main_kernel<<<NJC * (NAG / TI), THREADS>>>(W2);   // 16 x 8 = 128 CTAs
    combine_kernel<<<NAG * 64 / 256, 256>>>(b2, out);
}

// round 7
// speedup vs baseline: 2.1762x; 1.3290x over previous
#include <cuda_runtime.h>
#include <cstdint>
#include <math_constants.h>

#define NAG 1024
#define NJC 8           // j-chunks of 128
#define TJ  128         // j's per CTA
#define THREADS 256

__device__ float g_U[NAG * 128];
__device__ float g_Q[NAG * 128];
__device__ float g_partial[NJC * NAG * 64];

// ---------------- helpers ----------------
// pack two f32 -> f16x2 (lo = first arg, hi = second arg), round-nearest
__device__ __forceinline__ uint32_t pack_h2(float lo, float hi) {
    uint32_t r;
    asm("cvt.rn.f16x2.f32 %0, %1, %2;" : "=r"(r) : "f"(hi), "f"(lo));
    return r;
}

// mma.sync m16n8k16 f16, f32 accum: D += A(16x16 row) * B(16x8 col)
__device__ __forceinline__ void mma_f16(float* d,
                                        uint32_t a0, uint32_t a1, uint32_t a2, uint32_t a3,
                                        uint32_t b0, uint32_t b1) {
    asm volatile(
        "mma.sync.aligned.m16n8k16.row.col.f32.f16.f16.f32 "
        "{%0,%1,%2,%3}, {%4,%5,%6,%7}, {%8,%9}, {%0,%1,%2,%3};"
        : "+f"(d[0]), "+f"(d[1]), "+f"(d[2]), "+f"(d[3])
        : "r"(a0), "r"(a1), "r"(a2), "r"(a3), "r"(b0), "r"(b1));
}

// ---------------- Kernel 1: precompute U, Q ----------------
// U[a][m] = hidden[a]@W1[0:64,m] + b1[m] + (b_e + ends[a]@W_e)@W1[64:80,m]
// Q[a][m] = (ends[a]@W_e)@W1[64:80,m]
__global__ void precompute_kernel(const float* __restrict__ hidden,
                                  const float* __restrict__ track,
                                  const float* __restrict__ W_e,
                                  const float* __restrict__ b_e,
                                  const float* __restrict__ W1,
                                  const float* __restrict__ b1) {
    __shared__ float sh[64];
    __shared__ float sP[16];
    int a = blockIdx.x;
    int m = threadIdx.x;  // 0..127
    if (m < 64) sh[m] = hidden[a * 64 + m];
    if (m < 16) {
        float e0 = track[a * 16 + 14];  // group_track[a][7][0]
        float e1 = track[a * 16 + 15];  // group_track[a][7][1]
        sP[m] = e0 * W_e[m] + e1 * W_e[16 + m];
    }
    __syncthreads();
    float acc = b1[m];
#pragma unroll 8
    for (int h = 0; h < 64; h++) acc = fmaf(sh[h], W1[h * 128 + m], acc);
    float q = 0.f;
#pragma unroll
    for (int e = 0; e < 16; e++) {
        float w = W1[(64 + e) * 128 + m];
        q = fmaf(sP[e], w, q);
        acc = fmaf(b_e[e], w, acc);
    }
    g_Q[a * 128 + m] = q;
    g_U[a * 128 + m] = acc + q;
}

// ---------------- Kernel 2: Zpre[i,j,:] = relu(U[j]-Q[i]) @ W2, running max over j ----------------
// M = i (64 rows/CTA), N = 64, loop over 128 j's. No syncs/shuffles in the loop;
// max-over-j is a register running max (max and relu/+b2 commute, applied later).
// CTA: 8 warps = 4 i-groups(16 rows) x 2 n-halves(32 cols).
__global__ void __launch_bounds__(THREADS, 1)
main_kernel(const float* __restrict__ W2) {
    const int tid  = threadIdx.x;
    const int wid  = tid >> 5;
    const int lane = tid & 31;
    const int g = lane >> 2;            // groupID (0..7)
    const int c = lane & 3;             // threadID in group
    const int mg = wid >> 1;            // i-group 0..3
    const int nh = wid & 1;             // n-half 0..1

    const int jcc   = blockIdx.x & (NJC - 1);   // j-chunk (128 j's)
    const int ibase = (blockIdx.x >> 3) * 64;   // i-tile (64 i's)
    const int jbase = jcc * TJ;
    const int row0 = ibase + mg * 16 + g;       // first D/A row this thread covers

    // Q resident in registers (rows row0, row0+8), fp32.
    // Qa[4ks+{0,1,2,3}] = Q[row0][16ks + {2c, 2c+1, 2c+8, 2c+9}]; Qb: row0+8.
    float Qa[32], Qb[32];
    {
        const float* q0 = g_Q + row0 * 128;
        const float* q1 = g_Q + (row0 + 8) * 128;
#pragma unroll
        for (int ks = 0; ks < 8; ks++) {
            float2 p;
            p = *(const float2*)(q0 + 16 * ks + 2 * c);     Qa[4*ks+0]=p.x; Qa[4*ks+1]=p.y;
            p = *(const float2*)(q0 + 16 * ks + 2 * c + 8); Qa[4*ks+2]=p.x; Qa[4*ks+3]=p.y;
            p = *(const float2*)(q1 + 16 * ks + 2 * c);     Qb[4*ks+0]=p.x; Qb[4*ks+1]=p.y;
            p = *(const float2*)(q1 + 16 * ks + 2 * c + 8); Qb[4*ks+2]=p.x; Qb[4*ks+3]=p.y;
        }
    }

    // W2 fragments (f16x2), invariant over j.
    // Wf[nt][ks][0]: rows 16ks+2c, +1 (lo,hi), col n; Wf[..][1]: rows +8, +9.
    uint32_t Wf[4][8][2];
#pragma unroll
    for (int nt = 0; nt < 4; nt++) {
        const int n = nh * 32 + nt * 8 + g;
#pragma unroll
        for (int ks = 0; ks < 8; ks++) {
            const int r = 16 * ks + 2 * c;
            Wf[nt][ks][0] = pack_h2(__ldg(W2 + r * 64 + n),       __ldg(W2 + (r + 1) * 64 + n));
            Wf[nt][ks][1] = pack_h2(__ldg(W2 + (r + 8) * 64 + n), __ldg(W2 + (r + 9) * 64 + n));
        }
    }

    // Running max registers.
    float mx[4][4];
#pragma unroll
    for (int nt = 0; nt < 4; nt++)
#pragma unroll
        for (int r = 0; r < 4; r++) mx[nt][r] = -CUDART_INF_F;

    // U row buffer: Uv[2ks] = U[j][16ks+2c..+1], Uv[2ks+1] = [.. +8..+9]
    float2 Uv[16];
    {
        const float* Ur = g_U + jbase * 128;
#pragma unroll
        for (int ks = 0; ks < 8; ks++) {
            Uv[2*ks+0] = __ldg((const float2*)(Ur + 16 * ks + 2 * c));
            Uv[2*ks+1] = __ldg((const float2*)(Ur + 16 * ks + 2 * c + 8));
        }
    }

#pragma unroll 1
    for (int jj = 0; jj < TJ; jj++) {
        float d[4][4];
#pragma unroll
        for (int nt = 0; nt < 4; nt++)
#pragma unroll
            for (int r = 0; r < 4; r++) d[nt][r] = 0.f;

#pragma unroll
        for (int ks = 0; ks < 8; ks++) {
            const float2 u01 = Uv[2*ks+0];
            const float2 u89 = Uv[2*ks+1];
            // A rows: row0 (Qa) -> a0/a2 ; row0+8 (Qb) -> a1/a3
            const uint32_t a0 = pack_h2(fmaxf(u01.x - Qa[4*ks+0], 0.f),
                                        fmaxf(u01.y - Qa[4*ks+1], 0.f));
            const uint32_t a1 = pack_h2(fmaxf(u01.x - Qb[4*ks+0], 0.f),
                                        fmaxf(u01.y - Qb[4*ks+1], 0.f));
            const uint32_t a2 = pack_h2(fmaxf(u89.x - Qa[4*ks+2], 0.f),
                                        fmaxf(u89.y - Qa[4*ks+3], 0.f));
            const uint32_t a3 = pack_h2(fmaxf(u89.x - Qb[4*ks+2], 0.f),
                                        fmaxf(u89.y - Qb[4*ks+3], 0.f));
#pragma unroll
            for (int nt = 0; nt < 4; nt++)
                mma_f16(d[nt], a0, a1, a2, a3, Wf[nt][ks][0], Wf[nt][ks][1]);
        }

        // Prefetch next U row (WAR on Uv is safe: builds above consumed it).
        if (jj + 1 < TJ) {
            const float* Un = g_U + (jbase + jj + 1) * 128;
#pragma unroll
            for (int ks = 0; ks < 8; ks++) {
                Uv[2*ks+0] = __ldg((const float2*)(Un + 16 * ks + 2 * c));
                Uv[2*ks+1] = __ldg((const float2*)(Un + 16 * ks + 2 * c + 8));
            }
        }

        // Running max (D row g -> d0,d1 ; row g+8 -> d2,d3 ; cols 2c,2c+1)
#pragma unroll
        for (int nt = 0; nt < 4; nt++) {
            mx[nt][0] = fmaxf(mx[nt][0], d[nt][0]);
            mx[nt][1] = fmaxf(mx[nt][1], d[nt][1]);
            mx[nt][2] = fmaxf(mx[nt][2], d[nt][2]);
            mx[nt][3] = fmaxf(mx[nt][3], d[nt][3]);
        }
    }

    // Write partials: rows row0, row0+8; col = nh*32 + nt*8 + 2c (+1 contiguous)
    float* base = g_partial + jcc * (NAG * 64);
#pragma unroll
    for (int nt = 0; nt < 4; nt++) {
        const int col = nh * 32 + nt * 8 + 2 * c;
        *(float2*)(base + row0 * 64 + col)       = make_float2(mx[nt][0], mx[nt][1]);
        *(float2*)(base + (row0 + 8) * 64 + col) = make_float2(mx[nt][2], mx[nt][3]);
    }
}

// ---------------- Kernel 3: combine over j-chunks + relu(+b2) ----------------
__global__ void combine_kernel(const float* __restrict__ b2, float* __restrict__ out) {
    int idx = blockIdx.x * 256 + threadIdx.x;  // 0..65535 = i*64+n
    int n = idx & 63;
    float m = g_partial[idx];
#pragma unroll
    for (int ch = 1; ch < NJC; ch++)
        m = fmaxf(m, g_partial[ch * (NAG * 64) + idx]);
    out[idx] = fmaxf(m + b2[n], 0.f);
}

extern "C" void kernel_launch(void* const* d_in, const int* in_sizes, int n_in,
                              void* d_out, int out_size) {
    const float* hidden = (const float*)d_in[0];
    const float* track  = (const float*)d_in[1];
    const float* W_e    = (const float*)d_in[2];
    const float* b_e    = (const float*)d_in[3];
    const float* W1     = (const float*)d_in[4];
    const float* b1     = (const float*)d_in[5];
    const float* W2     = (const float*)d_in[6];
    const float* b2     = (const float*)d_in[7];
    float* out = (float*)d_out;

    precompute_kernel<<<NAG, 128>>>(hidden, track, W_e, b_e, W1, b1);
    main_kernel<<<NJC * (NAG / 64), THREADS>>>(W2);   // 8 x 16 = 128 CTAs
    combine_kernel<<<NAG * 64 / 256, 256>>>(b2, out);
}

// round 9
// speedup vs baseline: 2.5126x; 1.1546x over previous
#include <cuda_runtime.h>
#include <cuda_fp16.h>
#include <cstdint>
#include <math_constants.h>

#define NAG 1024
#define NJC 8           // j-chunks of 128
#define TJ  128         // j's per CTA
#define THREADS 256

__device__ __half g_Uh[NAG * 128];
__device__ __half g_Qh[NAG * 128];
__device__ float  g_partial[NJC * NAG * 64];

// ---------------- helpers ----------------
__device__ __forceinline__ uint32_t pack_h2(float lo, float hi) {
    uint32_t r;
    asm("cvt.rn.f16x2.f32 %0, %1, %2;" : "=r"(r) : "f"(hi), "f"(lo));
    return r;
}
__device__ __forceinline__ uint32_t h2u(__half2 h) {
    return *reinterpret_cast<uint32_t*>(&h);
}

// mma.sync m16n8k16 f16, f32 accum: D += A(16x16 row) * B(16x8 col)
__device__ __forceinline__ void mma_f16(float* d,
                                        uint32_t a0, uint32_t a1, uint32_t a2, uint32_t a3,
                                        uint32_t b0, uint32_t b1) {
    asm volatile(
        "mma.sync.aligned.m16n8k16.row.col.f32.f16.f16.f32 "
        "{%0,%1,%2,%3}, {%4,%5,%6,%7}, {%8,%9}, {%0,%1,%2,%3};"
        : "+f"(d[0]), "+f"(d[1]), "+f"(d[2]), "+f"(d[3])
        : "r"(a0), "r"(a1), "r"(a2), "r"(a3), "r"(b0), "r"(b1));
}

// ---------------- Kernel 1: precompute U, Q (fp16 out), 4 agents/block ----------------
// U[a][m] = hidden[a]@W1[0:64,m] + b1[m] + (b_e + ends[a]@W_e)@W1[64:80,m]
// Q[a][m] = (ends[a]@W_e)@W1[64:80,m]
__global__ void precompute_kernel(const float* __restrict__ hidden,
                                  const float* __restrict__ track,
                                  const float* __restrict__ W_e,
                                  const float* __restrict__ b_e,
                                  const float* __restrict__ W1,
                                  const float* __restrict__ b1) {
    __shared__ float sh[4][64];
    __shared__ float sP[4][16];
    const int a0 = blockIdx.x * 4;
    const int m = threadIdx.x;  // 0..127
    if (m < 64) {
#pragma unroll
        for (int q = 0; q < 4; q++) sh[q][m] = hidden[(a0 + q) * 64 + m];
    }
    if (m < 16) {
#pragma unroll
        for (int q = 0; q < 4; q++) {
            float e0 = track[(a0 + q) * 16 + 14];
            float e1 = track[(a0 + q) * 16 + 15];
            sP[q][m] = e0 * W_e[m] + e1 * W_e[16 + m];
        }
    }
    __syncthreads();
    float acc[4], qq[4];
    const float bias = b1[m];
#pragma unroll
    for (int q = 0; q < 4; q++) { acc[q] = bias; qq[q] = 0.f; }
#pragma unroll 8
    for (int h = 0; h < 64; h++) {
        const float w = W1[h * 128 + m];
#pragma unroll
        for (int q = 0; q < 4; q++) acc[q] = fmaf(sh[q][h], w, acc[q]);
    }
#pragma unroll
    for (int e = 0; e < 16; e++) {
        const float w = W1[(64 + e) * 128 + m];
        const float bw = b_e[e] * w;
#pragma unroll
        for (int q = 0; q < 4; q++) {
            qq[q] = fmaf(sP[q][e], w, qq[q]);
            acc[q] += bw;
        }
    }
#pragma unroll
    for (int q = 0; q < 4; q++) {
        g_Qh[(a0 + q) * 128 + m] = __float2half_rn(qq[q]);
        g_Uh[(a0 + q) * 128 + m] = __float2half_rn(acc[q] + qq[q]);
    }
}

// ---------------- Kernel 2: relu(U[j]-Q[i]) @ W2, running max over j ----------------
// M = i (64 rows/CTA), N = 64, loop over 128 j's. fp16x2 build, no syncs in loop.
// CTA: 8 warps = 4 i-groups(16 rows) x 2 n-halves(32 cols).
__global__ void __launch_bounds__(THREADS, 1)
main_kernel(const float* __restrict__ W2) {
    const int tid  = threadIdx.x;
    const int wid  = tid >> 5;
    const int lane = tid & 31;
    const int g = lane >> 2;            // groupID (0..7)
    const int c = lane & 3;             // threadID in group
    const int mg = wid >> 1;            // i-group 0..3
    const int nh = wid & 1;             // n-half 0..1

    const int jcc   = blockIdx.x & (NJC - 1);
    const int ibase = (blockIdx.x >> 3) * 64;
    const int jbase = jcc * TJ;
    const int row0 = ibase + mg * 16 + g;

    // Q fp16x2 resident: per ks, cols {16ks+2c,+1} and {16ks+2c+8,+9}, rows row0 / row0+8
    __half2 Qa01[8], Qa89[8], Qb01[8], Qb89[8];
    {
        const __half* q0 = g_Qh + row0 * 128;
        const __half* q1 = g_Qh + (row0 + 8) * 128;
#pragma unroll
        for (int ks = 0; ks < 8; ks++) {
            Qa01[ks] = *(const __half2*)(q0 + 16 * ks + 2 * c);
            Qa89[ks] = *(const __half2*)(q0 + 16 * ks + 2 * c + 8);
            Qb01[ks] = *(const __half2*)(q1 + 16 * ks + 2 * c);
            Qb89[ks] = *(const __half2*)(q1 + 16 * ks + 2 * c + 8);
        }
    }

    // W2 fragments (f16x2), invariant over j.
    uint32_t Wf[4][8][2];
#pragma unroll
    for (int nt = 0; nt < 4; nt++) {
        const int n = nh * 32 + nt * 8 + g;
#pragma unroll
        for (int ks = 0; ks < 8; ks++) {
            const int r = 16 * ks + 2 * c;
            Wf[nt][ks][0] = pack_h2(__ldg(W2 + r * 64 + n),       __ldg(W2 + (r + 1) * 64 + n));
            Wf[nt][ks][1] = pack_h2(__ldg(W2 + (r + 8) * 64 + n), __ldg(W2 + (r + 9) * 64 + n));
        }
    }

    float mx[4][4];
#pragma unroll
    for (int nt = 0; nt < 4; nt++)
#pragma unroll
        for (int r = 0; r < 4; r++) mx[nt][r] = -CUDART_INF_F;

    // U row buffer (fp16x2): Uv[2ks] = cols 16ks+2c..+1, Uv[2ks+1] = +8..+9
    __half2 Uv[16];
    {
        const __half* Ur = g_Uh + jbase * 128;
#pragma unroll
        for (int ks = 0; ks < 8; ks++) {
            Uv[2*ks+0] = *(const __half2*)(Ur + 16 * ks + 2 * c);
            Uv[2*ks+1] = *(const __half2*)(Ur + 16 * ks + 2 * c + 8);
        }
    }

    const __half2 hz = __float2half2_rn(0.f);

#pragma unroll 1
    for (int jj = 0; jj < TJ; jj++) {
        float d[4][4];
#pragma unroll
        for (int nt = 0; nt < 4; nt++)
#pragma unroll
            for (int r = 0; r < 4; r++) d[nt][r] = 0.f;

#pragma unroll
        for (int ks = 0; ks < 8; ks++) {
            const __half2 u01 = Uv[2*ks+0];
            const __half2 u89 = Uv[2*ks+1];
            // A rows: g=row0 (Qa) -> a0,a2 ; g+8=row0+8 (Qb) -> a1,a3
            const uint32_t a0 = h2u(__hmax2(__hsub2(u01, Qa01[ks]), hz));
            const uint32_t a1 = h2u(__hmax2(__hsub2(u01, Qb01[ks]), hz));
            const uint32_t a2 = h2u(__hmax2(__hsub2(u89, Qa89[ks]), hz));
            const uint32_t a3 = h2u(__hmax2(__hsub2(u89, Qb89[ks]), hz));
#pragma unroll
            for (int nt = 0; nt < 4; nt++)
                mma_f16(d[nt], a0, a1, a2, a3, Wf[nt][ks][0], Wf[nt][ks][1]);
        }

        // Prefetch next U row (WAR safe: builds above consumed Uv).
        if (jj + 1 < TJ) {
            const __half* Un = g_Uh + (jbase + jj + 1) * 128;
#pragma unroll
            for (int ks = 0; ks < 8; ks++) {
                Uv[2*ks+0] = *(const __half2*)(Un + 16 * ks + 2 * c);
                Uv[2*ks+1] = *(const __half2*)(Un + 16 * ks + 2 * c + 8);
            }
        }

        // Running max
#pragma unroll
        for (int nt = 0; nt < 4; nt++) {
            mx[nt][0] = fmaxf(mx[nt][0], d[nt][0]);
            mx[nt][1] = fmaxf(mx[nt][1], d[nt][1]);
            mx[nt][2] = fmaxf(mx[nt][2], d[nt][2]);
            mx[nt][3] = fmaxf(mx[nt][3], d[nt][3]);
        }
    }

    // Write partials: rows row0, row0+8; col = nh*32 + nt*8 + 2c (pair)
    float* base = g_partial + jcc * (NAG * 64);
#pragma unroll
    for (int nt = 0; nt < 4; nt++) {
        const int col = nh * 32 + nt * 8 + 2 * c;
        *(float2*)(base + row0 * 64 + col)       = make_float2(mx[nt][0], mx[nt][1]);
        *(float2*)(base + (row0 + 8) * 64 + col) = make_float2(mx[nt][2], mx[nt][3]);
    }
}

// ---------------- Kernel 3: combine over j-chunks + relu(+b2) ----------------
__global__ void combine_kernel(const float* __restrict__ b2, float* __restrict__ out) {
    int idx = blockIdx.x * 256 + threadIdx.x;  // i*64+n
    int n = idx & 63;
    float m = g_partial[idx];
#pragma unroll
    for (int ch = 1; ch < NJC; ch++)
        m = fmaxf(m, g_partial[ch * (NAG * 64) + idx]);
    out[idx] = fmaxf(m + b2[n], 0.f);
}

extern "C" void kernel_launch(void* const* d_in, const int* in_sizes, int n_in,
                              void* d_out, int out_size) {
    const float* hidden = (const float*)d_in[0];
    const float* track  = (const float*)d_in[1];
    const float* W_e    = (const float*)d_in[2];
    const float* b_e    = (const float*)d_in[3];
    const float* W1     = (const float*)d_in[4];
    const float* b1     = (const float*)d_in[5];
    const float* W2     = (const float*)d_in[6];
    const float* b2     = (const float*)d_in[7];
    float* out = (float*)d_out;

    precompute_kernel<<<NAG / 4, 128>>>(hidden, track, W_e, b_e, W1, b1);
    main_kernel<<<NJC * (NAG / 64), THREADS>>>(W2);   // 8 x 16 = 128 CTAs
    combine_kernel<<<NAG * 64 / 256, 256>>>(b2, out);
}